// round 7
// baseline (speedup 1.0000x reference)
#include <cuda_runtime.h>
#include <cstdint>

// FISTA denoiser, packed f32x2 stencil, scalar clamp, software-pipelined halos.
// One warp = two rows; each u64 register packs (row0[i], row1[i]).
// Iteration order: boundary elems {0,1,14,15} -> next-iter SHFLs -> interior.

#define LAM   10.0f
#define NIT   100
#define ROWN  512
#define EPL   16

typedef unsigned long long u64;

__device__ __forceinline__ u64 pk(float lo, float hi) {
    u64 r; asm("mov.b64 %0, {%1,%2};" : "=l"(r) : "f"(lo), "f"(hi)); return r;
}
__device__ __forceinline__ void upk(u64 v, float& lo, float& hi) {
    asm("mov.b64 {%0,%1}, %2;" : "=f"(lo), "=f"(hi) : "l"(v));
}
__device__ __forceinline__ u64 fma2(u64 a, u64 b, u64 c) {
    u64 d; asm("fma.rn.f32x2 %0, %1, %2, %3;" : "=l"(d) : "l"(a), "l"(b), "l"(c)); return d;
}
__device__ __forceinline__ u64 add2(u64 a, u64 b) {
    u64 d; asm("add.rn.f32x2 %0, %1, %2;" : "=l"(d) : "l"(a), "l"(b)); return d;
}
__device__ __forceinline__ u64 mul2(u64 a, u64 b) {
    u64 d; asm("mul.rn.f32x2 %0, %1, %2;" : "=l"(d) : "l"(a), "l"(b)); return d;
}
__device__ __forceinline__ u64 bc(float f) { return pk(f, f); }

// A = 1/(1+16*LAM) = 2*step ; B = LAM/(1+16*LAM) = 2*LAM*step
#define C_A (1.0f / (1.0f + 16.0f * LAM))
#define C_B (LAM  / (1.0f + 16.0f * LAM))

// ---- compile-time FISTA momentum table, pre-broadcast as u64 f32x2 pairs ----
constexpr u64 bcast_bits(float f) {
    unsigned b = __builtin_bit_cast(unsigned, f);
    return ((u64)b << 32) | (u64)b;
}
struct MTab { u64 m1p[NIT]; u64 mn[NIT]; };
constexpr MTab make_mtab() {
    MTab t{};
    double tt = 1.0;
    for (int i = 0; i < NIT; i++) {
        double s = 1.0 + 4.0 * tt * tt;
        double r = s;                         // Newton sqrt
        for (int k = 0; k < 64; k++) r = 0.5 * (r + s / r);
        double tn = 0.5 * (1.0 + r);
        double m  = (tt - 1.0) / tn;
        t.m1p[i] = bcast_bits((float)(1.0 + m));
        t.mn[i]  = bcast_bits((float)(-m));
        tt = tn;
    }
    return t;
}
__constant__ MTab c_mtab = make_mtab();

// One FISTA solve on the packed pair-of-rows. y: data (packed), x: output (packed).
__device__ __forceinline__ void solve2(const u64* __restrict__ y,
                                       u64* __restrict__ x,
                                       int lane)
{
    const unsigned FULL = 0xffffffffu;
    const u64 C0  = bc(1.0f - C_A - 6.0f * C_B);   // center tap
    const u64 C1  = bc(4.0f * C_B);                // +/-1 taps
    const u64 C2  = bc(-C_B);                      // +/-2 taps
    const u64 CA  = bc(C_A);                       // data-term coefficient
    const u64 B5  = bc(5.0f * C_B);
    const u64 BN2 = bc(-2.0f * C_B);
    const u64 B1  = bc(C_B);
    const u64 Z64 = 0ull;

    u64 z[EPL];
    #pragma unroll
    for (int i = 0; i < EPL; i++) { x[i] = y[i]; z[i] = y[i]; }  // proj(y)=y on [0,y]

    const bool l0 = (lane == 0), l31 = (lane == 31);

    // prologue halos from initial z
    u64 hm2 = __shfl_up_sync  (FULL, z[EPL - 2], 1);
    u64 hm1 = __shfl_up_sync  (FULL, z[EPL - 1], 1);
    u64 hp0 = __shfl_down_sync(FULL, z[0], 1);
    u64 hp1 = __shfl_down_sync(FULL, z[1], 1);
    if (l0)  { hm2 = Z64; hm1 = Z64; }
    if (l31) { hp0 = Z64; hp1 = Z64; }

    for (int it = 0; it < NIT; ++it) {
        // ze[k] = z_global[16*lane - 2 + k], k = 0..19  (snapshot of z)
        u64 ze[EPL + 4];
        ze[0] = hm2; ze[1] = hm1;
        #pragma unroll
        for (int i = 0; i < EPL; i++) ze[2 + i] = z[i];
        ze[EPL + 2] = hp0; ze[EPL + 3] = hp1;

        // momentum coefficients (pre-broadcast u64 pairs, one LDC.64 each)
        const u64 M1P = c_mtab.m1p[it];
        const u64 MN  = c_mtab.mn[it];

        // per-element update: 5-point stencil, clamp, momentum
        auto elem = [&](int i, u64 v) {
            // packed clamp onto [0, y] — scalar FMNMX on alu pipe
            float vl, vh, yl, yh;
            upk(v, vl, vh);
            upk(y[i], yl, yh);
            float xl = fminf(fmaxf(vl, 0.0f), yl);
            float xh = fminf(fmaxf(vh, 0.0f), yh);
            u64 xn = pk(xl, xh);
            // z_new = (1+m) x_new - m x_old
            u64 zn = fma2(M1P, xn, mul2(MN, x[i]));
            x[i] = xn;
            z[i] = zn;
        };
        auto stencil = [&](int i) -> u64 {
            // v = CA*y + C0*z + C1*(z[-1]+z[+1]) + C2*(z[-2]+z[+2])
            u64 s1 = add2(ze[i + 1], ze[i + 3]);
            u64 s2 = add2(ze[i],     ze[i + 4]);
            return fma2(CA, y[i],
                     fma2(C0, ze[i + 2],
                       fma2(C1, s1, mul2(C2, s2))));
        };

        // ---- group A: boundary elements 0, 1, 14, 15 (with exact D^T D fixups) ----
        {
            u64 v0 = stencil(0);
            if (l0) { v0 = fma2(B5, ze[2], v0); v0 = fma2(BN2, ze[3], v0); }
            elem(0, v0);

            u64 v1 = stencil(1);
            if (l0) { v1 = fma2(BN2, ze[2], v1); v1 = fma2(B1, ze[3], v1); }
            elem(1, v1);

            u64 ve = stencil(EPL - 2);
            if (l31) { ve = fma2(BN2, ze[EPL + 1], ve); ve = fma2(B1, ze[EPL], ve); }
            elem(EPL - 2, ve);

            u64 vf = stencil(EPL - 1);
            if (l31) { vf = fma2(B5, ze[EPL + 1], vf); vf = fma2(BN2, ze[EPL], vf); }
            elem(EPL - 1, vf);
        }

        // ---- issue next iteration's halo shuffles NOW (latency hidden by group B) ----
        hm2 = __shfl_up_sync  (FULL, z[EPL - 2], 1);
        hm1 = __shfl_up_sync  (FULL, z[EPL - 1], 1);
        hp0 = __shfl_down_sync(FULL, z[0], 1);
        hp1 = __shfl_down_sync(FULL, z[1], 1);
        if (l0)  { hm2 = Z64; hm1 = Z64; }
        if (l31) { hp0 = Z64; hp1 = Z64; }

        // ---- group B: interior elements 2..13 (read ze snapshot only) ----
        #pragma unroll
        for (int i = 2; i < EPL - 2; i++)
            elem(i, stencil(i));
    }
}

__global__ void __launch_bounds__(128, 4)
fista_denoise6_kernel(const float* __restrict__ in, float* __restrict__ out, int npairs)
{
    const int gwarp = (int)((blockIdx.x * (unsigned)blockDim.x + threadIdx.x) >> 5);
    const int lane  = threadIdx.x & 31;
    if (gwarp >= npairs) return;   // whole warp exits together

    const float* r0 = in + (size_t)(2 * gwarp) * ROWN + lane * EPL;
    const float* r1 = r0 + ROWN;

    u64 y[EPL];
    #pragma unroll
    for (int v = 0; v < EPL / 4; v++) {
        float4 a = reinterpret_cast<const float4*>(r0)[v];
        float4 b = reinterpret_cast<const float4*>(r1)[v];
        y[4 * v + 0] = pk(a.x, b.x);
        y[4 * v + 1] = pk(a.y, b.y);
        y[4 * v + 2] = pk(a.z, b.z);
        y[4 * v + 3] = pk(a.w, b.w);
    }

    u64 x[EPL];
    solve2(y, x, lane);                       // pass 1: y = input
    #pragma unroll
    for (int i = 0; i < EPL; i++) y[i] = x[i];
    solve2(y, x, lane);                       // pass 2: y = pass-1 output

    float* w0 = out + (size_t)(2 * gwarp) * ROWN + lane * EPL;
    float* w1 = w0 + ROWN;
    #pragma unroll
    for (int v = 0; v < EPL / 4; v++) {
        float4 a, b;
        upk(x[4 * v + 0], a.x, b.x);
        upk(x[4 * v + 1], a.y, b.y);
        upk(x[4 * v + 2], a.z, b.z);
        upk(x[4 * v + 3], a.w, b.w);
        reinterpret_cast<float4*>(w0)[v] = a;
        reinterpret_cast<float4*>(w1)[v] = b;
    }
}

extern "C" void kernel_launch(void* const* d_in, const int* in_sizes, int n_in,
                              void* d_out, int out_size)
{
    const float* in = (const float*)d_in[0];
    float* out = (float*)d_out;
    const int nelem  = in_sizes[0];           // 32*512*512
    const int nrows  = nelem / ROWN;          // 16384
    const int npairs = nrows / 2;             // 8192 warps
    const int warps_per_block = 128 / 32;     // 4
    const int nblocks = (npairs + warps_per_block - 1) / warps_per_block;
    fista_denoise6_kernel<<<nblocks, 128>>>(in, out, npairs);
}

// round 9
// speedup vs baseline: 1.0563x; 1.0563x over previous
#include <cuda_runtime.h>
#include <cstdint>

// FISTA denoiser, packed f32x2, uniform 5-point stencil with exact ghost
// boundary values (branch-free hot loop), occupancy-4 build.
// One warp = two rows; each u64 register packs (row0[i], row1[i]).
// Ghosts: h[-1] = 2z0 - z1, h[-2] = 3z0 - 2z1 (mirrored on the right) make
// the uniform [1,-4,6,-4,1] D^T D stencil exact at rows 0,1,510,511.

#define LAM   10.0f
#define NIT   100
#define ROWN  512
#define EPL   16

typedef unsigned long long u64;

__device__ __forceinline__ u64 pk(float lo, float hi) {
    u64 r; asm("mov.b64 %0, {%1,%2};" : "=l"(r) : "f"(lo), "f"(hi)); return r;
}
__device__ __forceinline__ void upk(u64 v, float& lo, float& hi) {
    asm("mov.b64 {%0,%1}, %2;" : "=f"(lo), "=f"(hi) : "l"(v));
}
__device__ __forceinline__ u64 fma2(u64 a, u64 b, u64 c) {
    u64 d; asm("fma.rn.f32x2 %0, %1, %2, %3;" : "=l"(d) : "l"(a), "l"(b), "l"(c)); return d;
}
__device__ __forceinline__ u64 add2(u64 a, u64 b) {
    u64 d; asm("add.rn.f32x2 %0, %1, %2;" : "=l"(d) : "l"(a), "l"(b)); return d;
}
__device__ __forceinline__ u64 mul2(u64 a, u64 b) {
    u64 d; asm("mul.rn.f32x2 %0, %1, %2;" : "=l"(d) : "l"(a), "l"(b)); return d;
}
__device__ __forceinline__ u64 bc(float f) { return pk(f, f); }

// A = 1/(1+16*LAM) = 2*step ; B = LAM/(1+16*LAM) = 2*LAM*step
#define C_A (1.0f / (1.0f + 16.0f * LAM))
#define C_B (LAM  / (1.0f + 16.0f * LAM))

// ---- compile-time FISTA momentum table, pre-broadcast as u64 f32x2 pairs ----
constexpr u64 bcast_bits(float f) {
    unsigned b = __builtin_bit_cast(unsigned, f);
    return ((u64)b << 32) | (u64)b;
}
struct MTab { u64 m1p[NIT]; u64 mn[NIT]; };
constexpr MTab make_mtab() {
    MTab t{};
    double tt = 1.0;
    for (int i = 0; i < NIT; i++) {
        double s = 1.0 + 4.0 * tt * tt;
        double r = s;                         // Newton sqrt
        for (int k = 0; k < 64; k++) r = 0.5 * (r + s / r);
        double tn = 0.5 * (1.0 + r);
        double m  = (tt - 1.0) / tn;
        t.m1p[i] = bcast_bits((float)(1.0 + m));
        t.mn[i]  = bcast_bits((float)(-m));
        tt = tn;
    }
    return t;
}
__constant__ MTab c_mtab = make_mtab();

// One FISTA solve on the packed pair-of-rows. y: data (packed), x: output (packed).
__device__ __forceinline__ void solve2(const u64* __restrict__ y,
                                       u64* __restrict__ x,
                                       int lane)
{
    const unsigned FULL = 0xffffffffu;
    const u64 C0  = bc(1.0f - C_A - 6.0f * C_B);   // center tap
    const u64 C1  = bc(4.0f * C_B);                // +/-1 taps
    const u64 C2  = bc(-C_B);                      // +/-2 taps
    const u64 CA  = bc(C_A);                       // data-term coefficient
    const u64 NEG1 = bc(-1.0f);

    u64 z[EPL];
    #pragma unroll
    for (int i = 0; i < EPL; i++) { x[i] = y[i]; z[i] = y[i]; }  // proj(y)=y on [0,y]

    const bool l0 = (lane == 0), l31 = (lane == 31);

    #pragma unroll 2
    for (int it = 0; it < NIT; ++it) {
        // 64-bit halo shuffles
        u64 zm2 = __shfl_up_sync  (FULL, z[EPL - 2], 1);
        u64 zm1 = __shfl_up_sync  (FULL, z[EPL - 1], 1);
        u64 zp0 = __shfl_down_sync(FULL, z[0], 1);
        u64 zp1 = __shfl_down_sync(FULL, z[1], 1);

        // ghost values making the uniform stencil exact at the boundaries
        // (computed unconditionally, selected only on lanes 0 / 31)
        {
            u64 dl  = fma2(NEG1, z[1], z[0]);         // z0 - z1
            u64 g1  = add2(z[0], dl);                 // 2 z0 - z1
            u64 g2  = add2(g1,  dl);                  // 3 z0 - 2 z1
            u64 dr  = fma2(NEG1, z[EPL - 2], z[EPL - 1]);  // z15 - z14
            u64 g3  = add2(z[EPL - 1], dr);           // 2 z15 - z14
            u64 g4  = add2(g3, dr);                   // 3 z15 - 2 z14
            zm1 = l0  ? g1 : zm1;
            zm2 = l0  ? g2 : zm2;
            zp0 = l31 ? g3 : zp0;
            zp1 = l31 ? g4 : zp1;
        }

        // ze[k] = z_ext[16*lane - 2 + k], k = 0..19  (snapshot of z)
        u64 ze[EPL + 4];
        ze[0] = zm2; ze[1] = zm1;
        #pragma unroll
        for (int i = 0; i < EPL; i++) ze[2 + i] = z[i];
        ze[EPL + 2] = zp0; ze[EPL + 3] = zp1;

        // momentum coefficients (pre-broadcast u64 pairs, one LDC.64 each)
        const u64 M1P = c_mtab.m1p[it];
        const u64 MN  = c_mtab.mn[it];

        // fully uniform, branch-free element loop
        #pragma unroll
        for (int i = 0; i < EPL; i++) {
            // v = CA*y + C0*z + C1*(z[-1]+z[+1]) + C2*(z[-2]+z[+2])
            u64 s1 = add2(ze[i + 1], ze[i + 3]);
            u64 s2 = add2(ze[i],     ze[i + 4]);
            u64 v  = fma2(CA, y[i],
                       fma2(C0, ze[i + 2],
                         fma2(C1, s1, mul2(C2, s2))));

            // clamp onto [0, y] — scalar FMNMX pairs on alu pipe
            float vl, vh, yl, yh;
            upk(v, vl, vh);
            upk(y[i], yl, yh);
            float xl = fminf(fmaxf(vl, 0.0f), yl);
            float xh = fminf(fmaxf(vh, 0.0f), yh);
            u64 xn = pk(xl, xh);

            // z_new = (1+m) x_new - m x_old
            u64 zn = fma2(M1P, xn, mul2(MN, x[i]));
            x[i] = xn;
            z[i] = zn;
        }
    }
}

__global__ void __launch_bounds__(128, 4)
fista_denoise9_kernel(const float* __restrict__ in, float* __restrict__ out, int npairs)
{
    const int gwarp = (int)((blockIdx.x * (unsigned)blockDim.x + threadIdx.x) >> 5);
    const int lane  = threadIdx.x & 31;
    if (gwarp >= npairs) return;   // whole warp exits together

    const float* r0 = in + (size_t)(2 * gwarp) * ROWN + lane * EPL;
    const float* r1 = r0 + ROWN;

    u64 y[EPL];
    #pragma unroll
    for (int v = 0; v < EPL / 4; v++) {
        float4 a = reinterpret_cast<const float4*>(r0)[v];
        float4 b = reinterpret_cast<const float4*>(r1)[v];
        y[4 * v + 0] = pk(a.x, b.x);
        y[4 * v + 1] = pk(a.y, b.y);
        y[4 * v + 2] = pk(a.z, b.z);
        y[4 * v + 3] = pk(a.w, b.w);
    }

    u64 x[EPL];
    solve2(y, x, lane);                       // pass 1: y = input
    #pragma unroll
    for (int i = 0; i < EPL; i++) y[i] = x[i];
    solve2(y, x, lane);                       // pass 2: y = pass-1 output

    float* w0 = out + (size_t)(2 * gwarp) * ROWN + lane * EPL;
    float* w1 = w0 + ROWN;
    #pragma unroll
    for (int v = 0; v < EPL / 4; v++) {
        float4 a, b;
        upk(x[4 * v + 0], a.x, b.x);
        upk(x[4 * v + 1], a.y, b.y);
        upk(x[4 * v + 2], a.z, b.z);
        upk(x[4 * v + 3], a.w, b.w);
        reinterpret_cast<float4*>(w0)[v] = a;
        reinterpret_cast<float4*>(w1)[v] = b;
    }
}

extern "C" void kernel_launch(void* const* d_in, const int* in_sizes, int n_in,
                              void* d_out, int out_size)
{
    const float* in = (const float*)d_in[0];
    float* out = (float*)d_out;
    const int nelem  = in_sizes[0];           // 32*512*512
    const int nrows  = nelem / ROWN;          // 16384
    const int npairs = nrows / 2;             // 8192 warps
    const int warps_per_block = 128 / 32;     // 4
    const int nblocks = (npairs + warps_per_block - 1) / warps_per_block;
    fista_denoise9_kernel<<<nblocks, 128>>>(in, out, npairs);
}